// round 11
// baseline (speedup 1.0000x reference)
#include <cuda_runtime.h>
#include <math.h>

#define NB   16
#define NT   8192
#define NH   256
#define NL   513
#define NOUT 5
#define TILE 16
#define NTILES 33   /* ceil(513/16) */

/* ---------------- scratch (static device globals: no runtime alloc) -------- */
__device__ float g_x [NB * NL * NH];   /* ph_agg (residual input)  */
__device__ float g_h1[NB * NL * NH];   /* LN1 output               */
__device__ float g_y1[NB * NL * NH];   /* silu(conv1) output       */
__device__ float g_x2[NB * NL * NH];   /* LN2 output (post input)  */
__device__ float g_np[NB * NL];        /* nonpad mask              */
__device__ int   g_off[NB * (NL + 1)]; /* segment frame offsets    */

__device__ __forceinline__ float sigm(float x) { return 1.0f / (1.0f + expf(-x)); }

/* ---------------- K0: per-batch cumsum of ph_bd -> segment offsets --------- */
__global__ void __launch_bounds__(1024) scan_kernel(const int* __restrict__ ph_bd)
{
    int b = blockIdx.x, tid = threadIdx.x;
    __shared__ int sh[1024];
    __shared__ int hist[NL];
    for (int i = tid; i < NL; i += 1024) hist[i] = 0;

    int v[8], c[8];
    int base = b * NT + tid * 8;
    int run = 0;
#pragma unroll
    for (int j = 0; j < 8; ++j) v[j] = ph_bd[base + j];
#pragma unroll
    for (int j = 0; j < 8; ++j) { run += v[j]; c[j] = run; }

    sh[tid] = run;
    __syncthreads();
    for (int o = 1; o < 1024; o <<= 1) {
        int add = (tid >= o) ? sh[tid - o] : 0;
        __syncthreads();
        sh[tid] += add;
        __syncthreads();
    }
    int excl = sh[tid] - run;
#pragma unroll
    for (int j = 0; j < 8; ++j) {
        int m = excl + c[j];
        if (m < NL) atomicAdd(&hist[m], 1);
    }
    __syncthreads();

    int cnt = (tid < NL) ? hist[tid] : 0;
    sh[tid] = cnt;
    __syncthreads();
    for (int o = 1; o < 1024; o <<= 1) {
        int add = (tid >= o) ? sh[tid - o] : 0;
        __syncthreads();
        sh[tid] += add;
        __syncthreads();
    }
    if (tid < NL) g_off[b * (NL + 1) + tid] = sh[tid] - cnt;
    if (tid == NL - 1) g_off[b * (NL + 1) + NL] = sh[tid];
}

/* block-wide sum over 256 threads, result broadcast to all threads */
__device__ __forceinline__ float blockSum256(float v, float* sm8)
{
    int tid = threadIdx.x;
#pragma unroll
    for (int o = 16; o; o >>= 1) v += __shfl_xor_sync(0xffffffffu, v, o);
    if ((tid & 31) == 0) sm8[tid >> 5] = v;
    __syncthreads();
    float s = sm8[0] + sm8[1] + sm8[2] + sm8[3] + sm8[4] + sm8[5] + sm8[6] + sm8[7];
    __syncthreads();
    return s;
}

/* ---------------- K1: fused attention + segment aggregation + LN1 ---------- */
__global__ void __launch_bounds__(256) agg_ln1_kernel(
    const float* __restrict__ feat, const float* __restrict__ w_attn,
    const float* __restrict__ b_attn, const float* __restrict__ ln_g,
    const float* __restrict__ ln_b)
{
    int b = blockIdx.y, p = blockIdx.x;
    int tid = threadIdx.x;
    int lane = tid & 31, wrp = tid >> 5;
    __shared__ float smr[8][16];
    __shared__ float smb[16];
    __shared__ float rsm[8];

    int start = g_off[b * (NL + 1) + p];
    int end   = g_off[b * (NL + 1) + p + 1];

    float w0 = w_attn[tid], w1 = w_attn[NH + tid];
    float ba0 = b_attn[0],  ba1 = b_attn[1];

    float acc = 0.f, den = 0.f;
    const float* fb = feat + ((long long)b * NT) * NH + tid;

    for (int t = start; t < end; t += 8) {
        int n = end - t; if (n > 8) n = 8;
        float f[8], p0[8], p1[8];
#pragma unroll
        for (int j = 0; j < 8; ++j) f[j] = (j < n) ? fb[(long long)(t + j) * NH] : 0.f;
#pragma unroll
        for (int j = 0; j < 8; ++j) { p0[j] = f[j] * w0; p1[j] = f[j] * w1; }
#pragma unroll
        for (int o = 16; o; o >>= 1) {
#pragma unroll
            for (int j = 0; j < 8; ++j) {
                p0[j] += __shfl_xor_sync(0xffffffffu, p0[j], o);
                p1[j] += __shfl_xor_sync(0xffffffffu, p1[j], o);
            }
        }
        if (lane == 0) {
#pragma unroll
            for (int j = 0; j < 8; ++j) { smr[wrp][j] = p0[j]; smr[wrp][8 + j] = p1[j]; }
        }
        __syncthreads();
        if (tid < 16) {
            float s = 0.f;
#pragma unroll
            for (int w = 0; w < 8; ++w) s += smr[w][tid];
            smb[tid] = s;
        }
        __syncthreads();
#pragma unroll
        for (int j = 0; j < 8; ++j) {
            if (j < n) {
                float a = 0.5f * (sigm(smb[j] + ba0) + sigm(smb[8 + j] + ba1));
                acc += a * f[j];
                den += a;
            }
        }
        __syncthreads();
    }

    float x = acc / (den + 1e-5f);

    float sabs = blockSum256(fabsf(x), rsm);
    float sx   = blockSum256(x, rsm);
    float m    = sx * (1.0f / NH);
    float d    = x - m;
    float sv   = blockSum256(d * d, rsm);
    float inv  = rsqrtf(sv * (1.0f / NH) + 1e-5f);

    long long idx = ((long long)b * NL + p) * NH + tid;
    g_x[idx]  = x;
    g_h1[idx] = d * inv * ln_g[tid] + ln_b[tid];
    if (tid == 0) g_np[b * NL + p] = (sabs > 0.f) ? 1.f : 0.f;
}

/* ---------------- K2: conv1 (k=3) * rsqrt(3) -> silu ----------------------- */
__global__ void __launch_bounds__(256) conv1_kernel(const float* __restrict__ W,
                                                    const float* __restrict__ bias)
{
    int b = blockIdx.y, l0 = blockIdx.x * TILE;
    int o = threadIdx.x;
    __shared__ float4 xs[TILE + 2][NH / 4];

    for (int idx = o; idx < (TILE + 2) * (NH / 4); idx += 256) {
        int row = idx >> 6, c = idx & 63;
        int l = l0 - 1 + row;
        float4 v = make_float4(0.f, 0.f, 0.f, 0.f);
        if (l >= 0 && l < NL)
            v = reinterpret_cast<const float4*>(g_h1 + ((long long)b * NL + l) * NH)[c];
        xs[row][c] = v;
    }
    __syncthreads();

    float acc[TILE];
#pragma unroll
    for (int p = 0; p < TILE; ++p) acc[p] = 0.f;

    const float4* wv = reinterpret_cast<const float4*>(W + o * (NH * 3));
#pragma unroll 2
    for (int i4 = 0; i4 < NH / 4; ++i4) {
        float4 wa = wv[i4 * 3 + 0];
        float4 wb = wv[i4 * 3 + 1];
        float4 wc = wv[i4 * 3 + 2];
        float4 r0 = xs[0][i4], r1 = xs[1][i4];
#pragma unroll
        for (int p = 0; p < TILE; ++p) {
            float4 r2 = xs[p + 2][i4];
            float a = acc[p];
            a = fmaf(r0.x, wa.x, a); a = fmaf(r1.x, wa.y, a); a = fmaf(r2.x, wa.z, a);
            a = fmaf(r0.y, wa.w, a); a = fmaf(r1.y, wb.x, a); a = fmaf(r2.y, wb.y, a);
            a = fmaf(r0.z, wb.z, a); a = fmaf(r1.z, wb.w, a); a = fmaf(r2.z, wc.x, a);
            a = fmaf(r0.w, wc.y, a); a = fmaf(r1.w, wc.z, a); a = fmaf(r2.w, wc.w, a);
            acc[p] = a;
            r0 = r1; r1 = r2;
        }
    }

    float bo = bias[o];
    const float rs3 = 0.5773502691896258f;
#pragma unroll
    for (int p = 0; p < TILE; ++p) {
        int l = l0 + p;
        if (l < NL) {
            float z = (acc[p] + bo) * rs3;
            g_y1[((long long)b * NL + l) * NH + o] = z * sigm(z);
        }
    }
}

/* ---------------- K3: conv2 (k=1) + residual + nonpad + LN2 ---------------- */
__global__ void __launch_bounds__(256) conv2_ln2_kernel(
    const float* __restrict__ W, const float* __restrict__ bias,
    const float* __restrict__ ln_g, const float* __restrict__ ln_b)
{
    int b = blockIdx.y, l0 = blockIdx.x * TILE;
    int o = threadIdx.x;
    int lane = o & 31, wrp = o >> 5;
    __shared__ float4 xs[TILE][NH / 4];
    __shared__ float  sm[TILE][NH + 1];

    for (int idx = o; idx < TILE * (NH / 4); idx += 256) {
        int row = idx >> 6, c = idx & 63;
        int l = l0 + row;
        float4 v = make_float4(0.f, 0.f, 0.f, 0.f);
        if (l < NL)
            v = reinterpret_cast<const float4*>(g_y1 + ((long long)b * NL + l) * NH)[c];
        xs[row][c] = v;
    }
    __syncthreads();

    float acc[TILE];
#pragma unroll
    for (int p = 0; p < TILE; ++p) acc[p] = 0.f;

    const float4* wv = reinterpret_cast<const float4*>(W + o * NH);
#pragma unroll 2
    for (int i4 = 0; i4 < NH / 4; ++i4) {
        float4 w = wv[i4];
#pragma unroll
        for (int p = 0; p < TILE; ++p) {
            float4 x = xs[p][i4];
            float a = acc[p];
            a = fmaf(x.x, w.x, a); a = fmaf(x.y, w.y, a);
            a = fmaf(x.z, w.z, a); a = fmaf(x.w, w.w, a);
            acc[p] = a;
        }
    }

    float bo = bias[o];
#pragma unroll
    for (int p = 0; p < TILE; ++p) {
        int l = l0 + p;
        float val = 0.f;
        if (l < NL) {
            float npv = g_np[b * NL + l];
            float xv  = g_x[((long long)b * NL + l) * NH + o];
            val = (xv + acc[p] + bo) * npv;
        }
        sm[p][o] = val;
    }
    __syncthreads();

    /* per-row LN over channels: warp wrp handles rows 2*wrp, 2*wrp+1 */
#pragma unroll
    for (int rr = 0; rr < 2; ++rr) {
        int p = wrp * 2 + rr;
        int l = l0 + p;
        if (l >= NL) continue;
        float vloc[8];
        float s = 0.f;
#pragma unroll
        for (int j = 0; j < 8; ++j) { vloc[j] = sm[p][lane + j * 32]; s += vloc[j]; }
#pragma unroll
        for (int off = 16; off; off >>= 1) s += __shfl_xor_sync(0xffffffffu, s, off);
        float m = s * (1.0f / NH);
        float v = 0.f;
#pragma unroll
        for (int j = 0; j < 8; ++j) { float d = vloc[j] - m; v += d * d; }
#pragma unroll
        for (int off = 16; off; off >>= 1) v += __shfl_xor_sync(0xffffffffu, v, off);
        float inv = rsqrtf(v * (1.0f / NH) + 1e-5f);
        float npv = g_np[b * NL + l];
#pragma unroll
        for (int j = 0; j < 8; ++j) {
            int c = lane + j * 32;
            float outv = ((vloc[j] - m) * inv * ln_g[c] + ln_b[c]) * npv;
            g_x2[((long long)b * NL + l) * NH + c] = outv;
        }
    }
}

/* ---------------- K4: post conv (k=3) + nonpad + output projection --------- */
__global__ void __launch_bounds__(256) post_out_kernel(
    const float* __restrict__ W, const float* __restrict__ bias,
    const float* __restrict__ w_out, const float* __restrict__ b_out,
    float* __restrict__ out)
{
    int b = blockIdx.y, l0 = blockIdx.x * TILE;
    int o = threadIdx.x;
    int lane = o & 31, wrp = o >> 5;
    __shared__ float4 xs[TILE + 2][NH / 4];
    __shared__ float  sm[TILE][NH + 1];

    for (int idx = o; idx < (TILE + 2) * (NH / 4); idx += 256) {
        int row = idx >> 6, c = idx & 63;
        int l = l0 - 1 + row;
        float4 v = make_float4(0.f, 0.f, 0.f, 0.f);
        if (l >= 0 && l < NL)
            v = reinterpret_cast<const float4*>(g_x2 + ((long long)b * NL + l) * NH)[c];
        xs[row][c] = v;
    }
    __syncthreads();

    float acc[TILE];
#pragma unroll
    for (int p = 0; p < TILE; ++p) acc[p] = 0.f;

    const float4* wv = reinterpret_cast<const float4*>(W + o * (NH * 3));
#pragma unroll 2
    for (int i4 = 0; i4 < NH / 4; ++i4) {
        float4 wa = wv[i4 * 3 + 0];
        float4 wb = wv[i4 * 3 + 1];
        float4 wc = wv[i4 * 3 + 2];
        float4 r0 = xs[0][i4], r1 = xs[1][i4];
#pragma unroll
        for (int p = 0; p < TILE; ++p) {
            float4 r2 = xs[p + 2][i4];
            float a = acc[p];
            a = fmaf(r0.x, wa.x, a); a = fmaf(r1.x, wa.y, a); a = fmaf(r2.x, wa.z, a);
            a = fmaf(r0.y, wa.w, a); a = fmaf(r1.y, wb.x, a); a = fmaf(r2.y, wb.y, a);
            a = fmaf(r0.z, wb.z, a); a = fmaf(r1.z, wb.w, a); a = fmaf(r2.z, wc.x, a);
            a = fmaf(r0.w, wc.y, a); a = fmaf(r1.w, wc.z, a); a = fmaf(r2.w, wc.w, a);
            acc[p] = a;
            r0 = r1; r1 = r2;
        }
    }

    float bo = bias[o];
#pragma unroll
    for (int p = 0; p < TILE; ++p) {
        int l = l0 + p;
        float val = 0.f;
        if (l < NL) val = (acc[p] + bo) * g_np[b * NL + l];
        sm[p][o] = val;
    }
    __syncthreads();

    /* final projection: warp wrp handles rows 2*wrp, 2*wrp+1, 5 logits each */
#pragma unroll
    for (int rr = 0; rr < 2; ++rr) {
        int p = wrp * 2 + rr;
        int l = l0 + p;
        if (l >= NL) continue;
#pragma unroll
        for (int c = 0; c < NOUT; ++c) {
            float s = 0.f;
#pragma unroll
            for (int j = 0; j < 8; ++j) {
                int idx = lane + j * 32;
                s += sm[p][idx] * w_out[c * NH + idx];
            }
#pragma unroll
            for (int off = 16; off; off >>= 1) s += __shfl_xor_sync(0xffffffffu, s, off);
            if (lane == 0) out[((long long)b * NL + l) * NOUT + c] = s + b_out[c];
        }
    }
}

/* ---------------- launch ---------------------------------------------------- */
extern "C" void kernel_launch(void* const* d_in, const int* in_sizes, int n_in,
                              void* d_out, int out_size)
{
    (void)n_in; (void)out_size;
    const float* feat  = (const float*)d_in[0];
    const int*   ph_bd = (const int*)d_in[1];
    /* ph_length may or may not be passed as a scalar input at index 2 */
    int base = (in_sizes[2] == 1) ? 3 : 2;
    const float* w_attn  = (const float*)d_in[base + 0];
    const float* b_attn  = (const float*)d_in[base + 1];
    const float* ln1_g   = (const float*)d_in[base + 2];
    const float* ln1_b   = (const float*)d_in[base + 3];
    const float* conv1_w = (const float*)d_in[base + 4];
    const float* conv1_b = (const float*)d_in[base + 5];
    const float* conv2_w = (const float*)d_in[base + 6];
    const float* conv2_b = (const float*)d_in[base + 7];
    const float* ln2_g   = (const float*)d_in[base + 8];
    const float* ln2_b   = (const float*)d_in[base + 9];
    const float* post_w  = (const float*)d_in[base + 10];
    const float* post_b  = (const float*)d_in[base + 11];
    const float* w_out   = (const float*)d_in[base + 12];
    const float* b_out   = (const float*)d_in[base + 13];
    float* out = (float*)d_out;

    scan_kernel<<<NB, 1024>>>(ph_bd);
    agg_ln1_kernel<<<dim3(NL, NB), 256>>>(feat, w_attn, b_attn, ln1_g, ln1_b);
    conv1_kernel<<<dim3(NTILES, NB), 256>>>(conv1_w, conv1_b);
    conv2_ln2_kernel<<<dim3(NTILES, NB), 256>>>(conv2_w, conv2_b, ln2_g, ln2_b);
    post_out_kernel<<<dim3(NTILES, NB), 256>>>(post_w, post_b, w_out, b_out, out);
}

// round 12
// speedup vs baseline: 1.0005x; 1.0005x over previous
#include <cuda_runtime.h>
#include <math.h>

#define NB   16
#define NT   8192
#define NH   256
#define NL   513
#define NOUT 5
#define TILE 16
#define NTILES 33   /* ceil(513/16) */

/* ---------------- scratch (static device globals: no runtime alloc) -------- */
__device__ float g_x [NB * NL * NH];   /* ph_agg (residual input)  */
__device__ float g_h1[NB * NL * NH];   /* LN1 output               */
__device__ float g_y1[NB * NL * NH];   /* silu(conv1) output       */
__device__ float g_x2[NB * NL * NH];   /* LN2 output (post input)  */
__device__ float g_np[NB * NL];        /* nonpad mask              */
__device__ int   g_off[NB * (NL + 1)]; /* segment frame offsets    */

__device__ __forceinline__ float sigm(float x) { return 1.0f / (1.0f + expf(-x)); }

/* ---------------- K0: per-batch cumsum of ph_bd -> segment offsets --------- */
__global__ void __launch_bounds__(1024) scan_kernel(const int* __restrict__ ph_bd)
{
    int b = blockIdx.x, tid = threadIdx.x;
    __shared__ int sh[1024];
    __shared__ int hist[NL];
    for (int i = tid; i < NL; i += 1024) hist[i] = 0;

    int v[8], c[8];
    int base = b * NT + tid * 8;
    int run = 0;
#pragma unroll
    for (int j = 0; j < 8; ++j) v[j] = ph_bd[base + j];
#pragma unroll
    for (int j = 0; j < 8; ++j) { run += v[j]; c[j] = run; }

    sh[tid] = run;
    __syncthreads();
    for (int o = 1; o < 1024; o <<= 1) {
        int add = (tid >= o) ? sh[tid - o] : 0;
        __syncthreads();
        sh[tid] += add;
        __syncthreads();
    }
    int excl = sh[tid] - run;
#pragma unroll
    for (int j = 0; j < 8; ++j) {
        int m = excl + c[j];
        if (m < NL) atomicAdd(&hist[m], 1);
    }
    __syncthreads();

    int cnt = (tid < NL) ? hist[tid] : 0;
    sh[tid] = cnt;
    __syncthreads();
    for (int o = 1; o < 1024; o <<= 1) {
        int add = (tid >= o) ? sh[tid - o] : 0;
        __syncthreads();
        sh[tid] += add;
        __syncthreads();
    }
    if (tid < NL) g_off[b * (NL + 1) + tid] = sh[tid] - cnt;
    if (tid == NL - 1) g_off[b * (NL + 1) + NL] = sh[tid];
}

/* block-wide sum over 256 threads, result broadcast to all threads */
__device__ __forceinline__ float blockSum256(float v, float* sm8)
{
    int tid = threadIdx.x;
#pragma unroll
    for (int o = 16; o; o >>= 1) v += __shfl_xor_sync(0xffffffffu, v, o);
    if ((tid & 31) == 0) sm8[tid >> 5] = v;
    __syncthreads();
    float s = sm8[0] + sm8[1] + sm8[2] + sm8[3] + sm8[4] + sm8[5] + sm8[6] + sm8[7];
    __syncthreads();
    return s;
}

/* ---------------- K1: fused attention + segment aggregation + LN1 ---------- */
__global__ void __launch_bounds__(256) agg_ln1_kernel(
    const float* __restrict__ feat, const float* __restrict__ w_attn,
    const float* __restrict__ b_attn, const float* __restrict__ ln_g,
    const float* __restrict__ ln_b)
{
    int b = blockIdx.y, p = blockIdx.x;
    int tid = threadIdx.x;
    int lane = tid & 31, wrp = tid >> 5;
    __shared__ float smr[8][16];
    __shared__ float smb[16];
    __shared__ float rsm[8];

    int start = g_off[b * (NL + 1) + p];
    int end   = g_off[b * (NL + 1) + p + 1];

    float w0 = w_attn[tid], w1 = w_attn[NH + tid];
    float ba0 = b_attn[0],  ba1 = b_attn[1];

    float acc = 0.f, den = 0.f;
    const float* fb = feat + ((long long)b * NT) * NH + tid;

    for (int t = start; t < end; t += 8) {
        int n = end - t; if (n > 8) n = 8;
        float f[8], p0[8], p1[8];
#pragma unroll
        for (int j = 0; j < 8; ++j) f[j] = (j < n) ? fb[(long long)(t + j) * NH] : 0.f;
#pragma unroll
        for (int j = 0; j < 8; ++j) { p0[j] = f[j] * w0; p1[j] = f[j] * w1; }
#pragma unroll
        for (int o = 16; o; o >>= 1) {
#pragma unroll
            for (int j = 0; j < 8; ++j) {
                p0[j] += __shfl_xor_sync(0xffffffffu, p0[j], o);
                p1[j] += __shfl_xor_sync(0xffffffffu, p1[j], o);
            }
        }
        if (lane == 0) {
#pragma unroll
            for (int j = 0; j < 8; ++j) { smr[wrp][j] = p0[j]; smr[wrp][8 + j] = p1[j]; }
        }
        __syncthreads();
        if (tid < 16) {
            float s = 0.f;
#pragma unroll
            for (int w = 0; w < 8; ++w) s += smr[w][tid];
            smb[tid] = s;
        }
        __syncthreads();
#pragma unroll
        for (int j = 0; j < 8; ++j) {
            if (j < n) {
                float a = 0.5f * (sigm(smb[j] + ba0) + sigm(smb[8 + j] + ba1));
                acc += a * f[j];
                den += a;
            }
        }
        __syncthreads();
    }

    float x = acc / (den + 1e-5f);

    float sabs = blockSum256(fabsf(x), rsm);
    float sx   = blockSum256(x, rsm);
    float m    = sx * (1.0f / NH);
    float d    = x - m;
    float sv   = blockSum256(d * d, rsm);
    float inv  = rsqrtf(sv * (1.0f / NH) + 1e-5f);

    long long idx = ((long long)b * NL + p) * NH + tid;
    g_x[idx]  = x;
    g_h1[idx] = d * inv * ln_g[tid] + ln_b[tid];
    if (tid == 0) g_np[b * NL + p] = (sabs > 0.f) ? 1.f : 0.f;
}

/* ---------------- K2: conv1 (k=3) * rsqrt(3) -> silu ----------------------- */
__global__ void __launch_bounds__(256) conv1_kernel(const float* __restrict__ W,
                                                    const float* __restrict__ bias)
{
    int b = blockIdx.y, l0 = blockIdx.x * TILE;
    int o = threadIdx.x;
    __shared__ float4 xs[TILE + 2][NH / 4];

    for (int idx = o; idx < (TILE + 2) * (NH / 4); idx += 256) {
        int row = idx >> 6, c = idx & 63;
        int l = l0 - 1 + row;
        float4 v = make_float4(0.f, 0.f, 0.f, 0.f);
        if (l >= 0 && l < NL)
            v = reinterpret_cast<const float4*>(g_h1 + ((long long)b * NL + l) * NH)[c];
        xs[row][c] = v;
    }
    __syncthreads();

    float acc[TILE];
#pragma unroll
    for (int p = 0; p < TILE; ++p) acc[p] = 0.f;

    const float4* wv = reinterpret_cast<const float4*>(W + o * (NH * 3));
#pragma unroll 2
    for (int i4 = 0; i4 < NH / 4; ++i4) {
        float4 wa = wv[i4 * 3 + 0];
        float4 wb = wv[i4 * 3 + 1];
        float4 wc = wv[i4 * 3 + 2];
        float4 r0 = xs[0][i4], r1 = xs[1][i4];
#pragma unroll
        for (int p = 0; p < TILE; ++p) {
            float4 r2 = xs[p + 2][i4];
            float a = acc[p];
            a = fmaf(r0.x, wa.x, a); a = fmaf(r1.x, wa.y, a); a = fmaf(r2.x, wa.z, a);
            a = fmaf(r0.y, wa.w, a); a = fmaf(r1.y, wb.x, a); a = fmaf(r2.y, wb.y, a);
            a = fmaf(r0.z, wb.z, a); a = fmaf(r1.z, wb.w, a); a = fmaf(r2.z, wc.x, a);
            a = fmaf(r0.w, wc.y, a); a = fmaf(r1.w, wc.z, a); a = fmaf(r2.w, wc.w, a);
            acc[p] = a;
            r0 = r1; r1 = r2;
        }
    }

    float bo = bias[o];
    const float rs3 = 0.5773502691896258f;
#pragma unroll
    for (int p = 0; p < TILE; ++p) {
        int l = l0 + p;
        if (l < NL) {
            float z = (acc[p] + bo) * rs3;
            g_y1[((long long)b * NL + l) * NH + o] = z * sigm(z);
        }
    }
}

/* ---------------- K3: conv2 (k=1) + residual + nonpad + LN2 ---------------- */
__global__ void __launch_bounds__(256) conv2_ln2_kernel(
    const float* __restrict__ W, const float* __restrict__ bias,
    const float* __restrict__ ln_g, const float* __restrict__ ln_b)
{
    int b = blockIdx.y, l0 = blockIdx.x * TILE;
    int o = threadIdx.x;
    int lane = o & 31, wrp = o >> 5;
    __shared__ float4 xs[TILE][NH / 4];
    __shared__ float  sm[TILE][NH + 1];

    for (int idx = o; idx < TILE * (NH / 4); idx += 256) {
        int row = idx >> 6, c = idx & 63;
        int l = l0 + row;
        float4 v = make_float4(0.f, 0.f, 0.f, 0.f);
        if (l < NL)
            v = reinterpret_cast<const float4*>(g_y1 + ((long long)b * NL + l) * NH)[c];
        xs[row][c] = v;
    }
    __syncthreads();

    float acc[TILE];
#pragma unroll
    for (int p = 0; p < TILE; ++p) acc[p] = 0.f;

    const float4* wv = reinterpret_cast<const float4*>(W + o * NH);
#pragma unroll 2
    for (int i4 = 0; i4 < NH / 4; ++i4) {
        float4 w = wv[i4];
#pragma unroll
        for (int p = 0; p < TILE; ++p) {
            float4 x = xs[p][i4];
            float a = acc[p];
            a = fmaf(x.x, w.x, a); a = fmaf(x.y, w.y, a);
            a = fmaf(x.z, w.z, a); a = fmaf(x.w, w.w, a);
            acc[p] = a;
        }
    }

    float bo = bias[o];
#pragma unroll
    for (int p = 0; p < TILE; ++p) {
        int l = l0 + p;
        float val = 0.f;
        if (l < NL) {
            float npv = g_np[b * NL + l];
            float xv  = g_x[((long long)b * NL + l) * NH + o];
            val = (xv + acc[p] + bo) * npv;
        }
        sm[p][o] = val;
    }
    __syncthreads();

    /* per-row LN over channels: warp wrp handles rows 2*wrp, 2*wrp+1 */
#pragma unroll
    for (int rr = 0; rr < 2; ++rr) {
        int p = wrp * 2 + rr;
        int l = l0 + p;
        if (l >= NL) continue;
        float vloc[8];
        float s = 0.f;
#pragma unroll
        for (int j = 0; j < 8; ++j) { vloc[j] = sm[p][lane + j * 32]; s += vloc[j]; }
#pragma unroll
        for (int off = 16; off; off >>= 1) s += __shfl_xor_sync(0xffffffffu, s, off);
        float m = s * (1.0f / NH);
        float v = 0.f;
#pragma unroll
        for (int j = 0; j < 8; ++j) { float d = vloc[j] - m; v += d * d; }
#pragma unroll
        for (int off = 16; off; off >>= 1) v += __shfl_xor_sync(0xffffffffu, v, off);
        float inv = rsqrtf(v * (1.0f / NH) + 1e-5f);
        float npv = g_np[b * NL + l];
#pragma unroll
        for (int j = 0; j < 8; ++j) {
            int c = lane + j * 32;
            float outv = ((vloc[j] - m) * inv * ln_g[c] + ln_b[c]) * npv;
            g_x2[((long long)b * NL + l) * NH + c] = outv;
        }
    }
}

/* ---------------- K4: post conv (k=3) + nonpad + output projection --------- */
__global__ void __launch_bounds__(256) post_out_kernel(
    const float* __restrict__ W, const float* __restrict__ bias,
    const float* __restrict__ w_out, const float* __restrict__ b_out,
    float* __restrict__ out)
{
    int b = blockIdx.y, l0 = blockIdx.x * TILE;
    int o = threadIdx.x;
    int lane = o & 31, wrp = o >> 5;
    __shared__ float4 xs[TILE + 2][NH / 4];
    __shared__ float  sm[TILE][NH + 1];

    for (int idx = o; idx < (TILE + 2) * (NH / 4); idx += 256) {
        int row = idx >> 6, c = idx & 63;
        int l = l0 - 1 + row;
        float4 v = make_float4(0.f, 0.f, 0.f, 0.f);
        if (l >= 0 && l < NL)
            v = reinterpret_cast<const float4*>(g_x2 + ((long long)b * NL + l) * NH)[c];
        xs[row][c] = v;
    }
    __syncthreads();

    float acc[TILE];
#pragma unroll
    for (int p = 0; p < TILE; ++p) acc[p] = 0.f;

    const float4* wv = reinterpret_cast<const float4*>(W + o * (NH * 3));
#pragma unroll 2
    for (int i4 = 0; i4 < NH / 4; ++i4) {
        float4 wa = wv[i4 * 3 + 0];
        float4 wb = wv[i4 * 3 + 1];
        float4 wc = wv[i4 * 3 + 2];
        float4 r0 = xs[0][i4], r1 = xs[1][i4];
#pragma unroll
        for (int p = 0; p < TILE; ++p) {
            float4 r2 = xs[p + 2][i4];
            float a = acc[p];
            a = fmaf(r0.x, wa.x, a); a = fmaf(r1.x, wa.y, a); a = fmaf(r2.x, wa.z, a);
            a = fmaf(r0.y, wa.w, a); a = fmaf(r1.y, wb.x, a); a = fmaf(r2.y, wb.y, a);
            a = fmaf(r0.z, wb.z, a); a = fmaf(r1.z, wb.w, a); a = fmaf(r2.z, wc.x, a);
            a = fmaf(r0.w, wc.y, a); a = fmaf(r1.w, wc.z, a); a = fmaf(r2.w, wc.w, a);
            acc[p] = a;
            r0 = r1; r1 = r2;
        }
    }

    float bo = bias[o];
#pragma unroll
    for (int p = 0; p < TILE; ++p) {
        int l = l0 + p;
        float val = 0.f;
        if (l < NL) val = (acc[p] + bo) * g_np[b * NL + l];
        sm[p][o] = val;
    }
    __syncthreads();

    /* final projection: warp wrp handles rows 2*wrp, 2*wrp+1, 5 logits each */
#pragma unroll
    for (int rr = 0; rr < 2; ++rr) {
        int p = wrp * 2 + rr;
        int l = l0 + p;
        if (l >= NL) continue;
#pragma unroll
        for (int c = 0; c < NOUT; ++c) {
            float s = 0.f;
#pragma unroll
            for (int j = 0; j < 8; ++j) {
                int idx = lane + j * 32;
                s += sm[p][idx] * w_out[c * NH + idx];
            }
#pragma unroll
            for (int off = 16; off; off >>= 1) s += __shfl_xor_sync(0xffffffffu, s, off);
            if (lane == 0) out[((long long)b * NL + l) * NOUT + c] = s + b_out[c];
        }
    }
}

/* ---------------- launch ---------------------------------------------------- */
extern "C" void kernel_launch(void* const* d_in, const int* in_sizes, int n_in,
                              void* d_out, int out_size)
{
    (void)n_in; (void)out_size;
    const float* feat  = (const float*)d_in[0];
    const int*   ph_bd = (const int*)d_in[1];
    /* ph_length may or may not be passed as a scalar input at index 2 */
    int base = (in_sizes[2] == 1) ? 3 : 2;
    const float* w_attn  = (const float*)d_in[base + 0];
    const float* b_attn  = (const float*)d_in[base + 1];
    const float* ln1_g   = (const float*)d_in[base + 2];
    const float* ln1_b   = (const float*)d_in[base + 3];
    const float* conv1_w = (const float*)d_in[base + 4];
    const float* conv1_b = (const float*)d_in[base + 5];
    const float* conv2_w = (const float*)d_in[base + 6];
    const float* conv2_b = (const float*)d_in[base + 7];
    const float* ln2_g   = (const float*)d_in[base + 8];
    const float* ln2_b   = (const float*)d_in[base + 9];
    const float* post_w  = (const float*)d_in[base + 10];
    const float* post_b  = (const float*)d_in[base + 11];
    const float* w_out   = (const float*)d_in[base + 12];
    const float* b_out   = (const float*)d_in[base + 13];
    float* out = (float*)d_out;

    scan_kernel<<<NB, 1024>>>(ph_bd);
    agg_ln1_kernel<<<dim3(NL, NB), 256>>>(feat, w_attn, b_attn, ln1_g, ln1_b);
    conv1_kernel<<<dim3(NTILES, NB), 256>>>(conv1_w, conv1_b);
    conv2_ln2_kernel<<<dim3(NTILES, NB), 256>>>(conv2_w, conv2_b, ln2_g, ln2_b);
    post_out_kernel<<<dim3(NTILES, NB), 256>>>(post_w, post_b, w_out, b_out, out);
}

// round 13
// speedup vs baseline: 1.0021x; 1.0017x over previous
#include <cuda_runtime.h>
#include <math.h>

#define NB   16
#define NT   8192
#define NH   256
#define NL   513
#define NOUT 5
#define TILE 16
#define NTILES 33   /* ceil(513/16) */

/* ---------------- scratch (static device globals: no runtime alloc) -------- */
__device__ float g_x [NB * NL * NH];   /* ph_agg (residual input)  */
__device__ float g_h1[NB * NL * NH];   /* LN1 output               */
__device__ float g_y1[NB * NL * NH];   /* silu(conv1) output       */
__device__ float g_x2[NB * NL * NH];   /* LN2 output (post input)  */
__device__ float g_np[NB * NL];        /* nonpad mask              */
__device__ int   g_off[NB * (NL + 1)]; /* segment frame offsets    */

__device__ __forceinline__ float sigm(float x) { return 1.0f / (1.0f + expf(-x)); }

/* ---------------- K0: per-batch cumsum of ph_bd -> segment offsets --------- */
__global__ void __launch_bounds__(1024) scan_kernel(const int* __restrict__ ph_bd)
{
    int b = blockIdx.x, tid = threadIdx.x;
    __shared__ int sh[1024];
    __shared__ int hist[NL];
    for (int i = tid; i < NL; i += 1024) hist[i] = 0;

    int v[8], c[8];
    int base = b * NT + tid * 8;
    int run = 0;
#pragma unroll
    for (int j = 0; j < 8; ++j) v[j] = ph_bd[base + j];
#pragma unroll
    for (int j = 0; j < 8; ++j) { run += v[j]; c[j] = run; }

    sh[tid] = run;
    __syncthreads();
    for (int o = 1; o < 1024; o <<= 1) {
        int add = (tid >= o) ? sh[tid - o] : 0;
        __syncthreads();
        sh[tid] += add;
        __syncthreads();
    }
    int excl = sh[tid] - run;
#pragma unroll
    for (int j = 0; j < 8; ++j) {
        int m = excl + c[j];
        if (m < NL) atomicAdd(&hist[m], 1);
    }
    __syncthreads();

    int cnt = (tid < NL) ? hist[tid] : 0;
    sh[tid] = cnt;
    __syncthreads();
    for (int o = 1; o < 1024; o <<= 1) {
        int add = (tid >= o) ? sh[tid - o] : 0;
        __syncthreads();
        sh[tid] += add;
        __syncthreads();
    }
    if (tid < NL) g_off[b * (NL + 1) + tid] = sh[tid] - cnt;
    if (tid == NL - 1) g_off[b * (NL + 1) + NL] = sh[tid];
}

/* block-wide sum over 256 threads, result broadcast to all threads */
__device__ __forceinline__ float blockSum256(float v, float* sm8)
{
    int tid = threadIdx.x;
#pragma unroll
    for (int o = 16; o; o >>= 1) v += __shfl_xor_sync(0xffffffffu, v, o);
    if ((tid & 31) == 0) sm8[tid >> 5] = v;
    __syncthreads();
    float s = sm8[0] + sm8[1] + sm8[2] + sm8[3] + sm8[4] + sm8[5] + sm8[6] + sm8[7];
    __syncthreads();
    return s;
}

/* ---------------- K1: fused attention + segment aggregation + LN1 ---------- */
__global__ void __launch_bounds__(256) agg_ln1_kernel(
    const float* __restrict__ feat, const float* __restrict__ w_attn,
    const float* __restrict__ b_attn, const float* __restrict__ ln_g,
    const float* __restrict__ ln_b)
{
    int b = blockIdx.y, p = blockIdx.x;
    int tid = threadIdx.x;
    int lane = tid & 31, wrp = tid >> 5;
    __shared__ float smr[8][16];
    __shared__ float smb[16];
    __shared__ float rsm[8];

    int start = g_off[b * (NL + 1) + p];
    int end   = g_off[b * (NL + 1) + p + 1];

    float w0 = w_attn[tid], w1 = w_attn[NH + tid];
    float ba0 = b_attn[0],  ba1 = b_attn[1];

    float acc = 0.f, den = 0.f;
    const float* fb = feat + ((long long)b * NT) * NH + tid;

    for (int t = start; t < end; t += 8) {
        int n = end - t; if (n > 8) n = 8;
        float f[8], p0[8], p1[8];
#pragma unroll
        for (int j = 0; j < 8; ++j) f[j] = (j < n) ? fb[(long long)(t + j) * NH] : 0.f;
#pragma unroll
        for (int j = 0; j < 8; ++j) { p0[j] = f[j] * w0; p1[j] = f[j] * w1; }
#pragma unroll
        for (int o = 16; o; o >>= 1) {
#pragma unroll
            for (int j = 0; j < 8; ++j) {
                p0[j] += __shfl_xor_sync(0xffffffffu, p0[j], o);
                p1[j] += __shfl_xor_sync(0xffffffffu, p1[j], o);
            }
        }
        if (lane == 0) {
#pragma unroll
            for (int j = 0; j < 8; ++j) { smr[wrp][j] = p0[j]; smr[wrp][8 + j] = p1[j]; }
        }
        __syncthreads();
        if (tid < 16) {
            float s = 0.f;
#pragma unroll
            for (int w = 0; w < 8; ++w) s += smr[w][tid];
            smb[tid] = s;
        }
        __syncthreads();
#pragma unroll
        for (int j = 0; j < 8; ++j) {
            if (j < n) {
                float a = 0.5f * (sigm(smb[j] + ba0) + sigm(smb[8 + j] + ba1));
                acc += a * f[j];
                den += a;
            }
        }
        __syncthreads();
    }

    float x = acc / (den + 1e-5f);

    float sabs = blockSum256(fabsf(x), rsm);
    float sx   = blockSum256(x, rsm);
    float m    = sx * (1.0f / NH);
    float d    = x - m;
    float sv   = blockSum256(d * d, rsm);
    float inv  = rsqrtf(sv * (1.0f / NH) + 1e-5f);

    long long idx = ((long long)b * NL + p) * NH + tid;
    g_x[idx]  = x;
    g_h1[idx] = d * inv * ln_g[tid] + ln_b[tid];
    if (tid == 0) g_np[b * NL + p] = (sabs > 0.f) ? 1.f : 0.f;
}

/* ---------------- K2: conv1 (k=3) * rsqrt(3) -> silu ----------------------- */
__global__ void __launch_bounds__(256) conv1_kernel(const float* __restrict__ W,
                                                    const float* __restrict__ bias)
{
    int b = blockIdx.y, l0 = blockIdx.x * TILE;
    int o = threadIdx.x;
    __shared__ float4 xs[TILE + 2][NH / 4];

    for (int idx = o; idx < (TILE + 2) * (NH / 4); idx += 256) {
        int row = idx >> 6, c = idx & 63;
        int l = l0 - 1 + row;
        float4 v = make_float4(0.f, 0.f, 0.f, 0.f);
        if (l >= 0 && l < NL)
            v = reinterpret_cast<const float4*>(g_h1 + ((long long)b * NL + l) * NH)[c];
        xs[row][c] = v;
    }
    __syncthreads();

    float acc[TILE];
#pragma unroll
    for (int p = 0; p < TILE; ++p) acc[p] = 0.f;

    const float4* wv = reinterpret_cast<const float4*>(W + o * (NH * 3));
#pragma unroll 2
    for (int i4 = 0; i4 < NH / 4; ++i4) {
        float4 wa = wv[i4 * 3 + 0];
        float4 wb = wv[i4 * 3 + 1];
        float4 wc = wv[i4 * 3 + 2];
        float4 r0 = xs[0][i4], r1 = xs[1][i4];
#pragma unroll
        for (int p = 0; p < TILE; ++p) {
            float4 r2 = xs[p + 2][i4];
            float a = acc[p];
            a = fmaf(r0.x, wa.x, a); a = fmaf(r1.x, wa.y, a); a = fmaf(r2.x, wa.z, a);
            a = fmaf(r0.y, wa.w, a); a = fmaf(r1.y, wb.x, a); a = fmaf(r2.y, wb.y, a);
            a = fmaf(r0.z, wb.z, a); a = fmaf(r1.z, wb.w, a); a = fmaf(r2.z, wc.x, a);
            a = fmaf(r0.w, wc.y, a); a = fmaf(r1.w, wc.z, a); a = fmaf(r2.w, wc.w, a);
            acc[p] = a;
            r0 = r1; r1 = r2;
        }
    }

    float bo = bias[o];
    const float rs3 = 0.5773502691896258f;
#pragma unroll
    for (int p = 0; p < TILE; ++p) {
        int l = l0 + p;
        if (l < NL) {
            float z = (acc[p] + bo) * rs3;
            g_y1[((long long)b * NL + l) * NH + o] = z * sigm(z);
        }
    }
}

/* ---------------- K3: conv2 (k=1) + residual + nonpad + LN2 ---------------- */
__global__ void __launch_bounds__(256) conv2_ln2_kernel(
    const float* __restrict__ W, const float* __restrict__ bias,
    const float* __restrict__ ln_g, const float* __restrict__ ln_b)
{
    int b = blockIdx.y, l0 = blockIdx.x * TILE;
    int o = threadIdx.x;
    int lane = o & 31, wrp = o >> 5;
    __shared__ float4 xs[TILE][NH / 4];
    __shared__ float  sm[TILE][NH + 1];

    for (int idx = o; idx < TILE * (NH / 4); idx += 256) {
        int row = idx >> 6, c = idx & 63;
        int l = l0 + row;
        float4 v = make_float4(0.f, 0.f, 0.f, 0.f);
        if (l < NL)
            v = reinterpret_cast<const float4*>(g_y1 + ((long long)b * NL + l) * NH)[c];
        xs[row][c] = v;
    }
    __syncthreads();

    float acc[TILE];
#pragma unroll
    for (int p = 0; p < TILE; ++p) acc[p] = 0.f;

    const float4* wv = reinterpret_cast<const float4*>(W + o * NH);
#pragma unroll 2
    for (int i4 = 0; i4 < NH / 4; ++i4) {
        float4 w = wv[i4];
#pragma unroll
        for (int p = 0; p < TILE; ++p) {
            float4 x = xs[p][i4];
            float a = acc[p];
            a = fmaf(x.x, w.x, a); a = fmaf(x.y, w.y, a);
            a = fmaf(x.z, w.z, a); a = fmaf(x.w, w.w, a);
            acc[p] = a;
        }
    }

    float bo = bias[o];
#pragma unroll
    for (int p = 0; p < TILE; ++p) {
        int l = l0 + p;
        float val = 0.f;
        if (l < NL) {
            float npv = g_np[b * NL + l];
            float xv  = g_x[((long long)b * NL + l) * NH + o];
            val = (xv + acc[p] + bo) * npv;
        }
        sm[p][o] = val;
    }
    __syncthreads();

    /* per-row LN over channels: warp wrp handles rows 2*wrp, 2*wrp+1 */
#pragma unroll
    for (int rr = 0; rr < 2; ++rr) {
        int p = wrp * 2 + rr;
        int l = l0 + p;
        if (l >= NL) continue;
        float vloc[8];
        float s = 0.f;
#pragma unroll
        for (int j = 0; j < 8; ++j) { vloc[j] = sm[p][lane + j * 32]; s += vloc[j]; }
#pragma unroll
        for (int off = 16; off; off >>= 1) s += __shfl_xor_sync(0xffffffffu, s, off);
        float m = s * (1.0f / NH);
        float v = 0.f;
#pragma unroll
        for (int j = 0; j < 8; ++j) { float d = vloc[j] - m; v += d * d; }
#pragma unroll
        for (int off = 16; off; off >>= 1) v += __shfl_xor_sync(0xffffffffu, v, off);
        float inv = rsqrtf(v * (1.0f / NH) + 1e-5f);
        float npv = g_np[b * NL + l];
#pragma unroll
        for (int j = 0; j < 8; ++j) {
            int c = lane + j * 32;
            float outv = ((vloc[j] - m) * inv * ln_g[c] + ln_b[c]) * npv;
            g_x2[((long long)b * NL + l) * NH + c] = outv;
        }
    }
}

/* ---------------- K4: post conv (k=3) + nonpad + output projection --------- */
__global__ void __launch_bounds__(256) post_out_kernel(
    const float* __restrict__ W, const float* __restrict__ bias,
    const float* __restrict__ w_out, const float* __restrict__ b_out,
    float* __restrict__ out)
{
    int b = blockIdx.y, l0 = blockIdx.x * TILE;
    int o = threadIdx.x;
    int lane = o & 31, wrp = o >> 5;
    __shared__ float4 xs[TILE + 2][NH / 4];
    __shared__ float  sm[TILE][NH + 1];

    for (int idx = o; idx < (TILE + 2) * (NH / 4); idx += 256) {
        int row = idx >> 6, c = idx & 63;
        int l = l0 - 1 + row;
        float4 v = make_float4(0.f, 0.f, 0.f, 0.f);
        if (l >= 0 && l < NL)
            v = reinterpret_cast<const float4*>(g_x2 + ((long long)b * NL + l) * NH)[c];
        xs[row][c] = v;
    }
    __syncthreads();

    float acc[TILE];
#pragma unroll
    for (int p = 0; p < TILE; ++p) acc[p] = 0.f;

    const float4* wv = reinterpret_cast<const float4*>(W + o * (NH * 3));
#pragma unroll 2
    for (int i4 = 0; i4 < NH / 4; ++i4) {
        float4 wa = wv[i4 * 3 + 0];
        float4 wb = wv[i4 * 3 + 1];
        float4 wc = wv[i4 * 3 + 2];
        float4 r0 = xs[0][i4], r1 = xs[1][i4];
#pragma unroll
        for (int p = 0; p < TILE; ++p) {
            float4 r2 = xs[p + 2][i4];
            float a = acc[p];
            a = fmaf(r0.x, wa.x, a); a = fmaf(r1.x, wa.y, a); a = fmaf(r2.x, wa.z, a);
            a = fmaf(r0.y, wa.w, a); a = fmaf(r1.y, wb.x, a); a = fmaf(r2.y, wb.y, a);
            a = fmaf(r0.z, wb.z, a); a = fmaf(r1.z, wb.w, a); a = fmaf(r2.z, wc.x, a);
            a = fmaf(r0.w, wc.y, a); a = fmaf(r1.w, wc.z, a); a = fmaf(r2.w, wc.w, a);
            acc[p] = a;
            r0 = r1; r1 = r2;
        }
    }

    float bo = bias[o];
#pragma unroll
    for (int p = 0; p < TILE; ++p) {
        int l = l0 + p;
        float val = 0.f;
        if (l < NL) val = (acc[p] + bo) * g_np[b * NL + l];
        sm[p][o] = val;
    }
    __syncthreads();

    /* final projection: warp wrp handles rows 2*wrp, 2*wrp+1, 5 logits each */
#pragma unroll
    for (int rr = 0; rr < 2; ++rr) {
        int p = wrp * 2 + rr;
        int l = l0 + p;
        if (l >= NL) continue;
#pragma unroll
        for (int c = 0; c < NOUT; ++c) {
            float s = 0.f;
#pragma unroll
            for (int j = 0; j < 8; ++j) {
                int idx = lane + j * 32;
                s += sm[p][idx] * w_out[c * NH + idx];
            }
#pragma unroll
            for (int off = 16; off; off >>= 1) s += __shfl_xor_sync(0xffffffffu, s, off);
            if (lane == 0) out[((long long)b * NL + l) * NOUT + c] = s + b_out[c];
        }
    }
}

/* ---------------- launch ---------------------------------------------------- */
extern "C" void kernel_launch(void* const* d_in, const int* in_sizes, int n_in,
                              void* d_out, int out_size)
{
    (void)n_in; (void)out_size;
    const float* feat  = (const float*)d_in[0];
    const int*   ph_bd = (const int*)d_in[1];
    /* ph_length may or may not be passed as a scalar input at index 2 */
    int base = (in_sizes[2] == 1) ? 3 : 2;
    const float* w_attn  = (const float*)d_in[base + 0];
    const float* b_attn  = (const float*)d_in[base + 1];
    const float* ln1_g   = (const float*)d_in[base + 2];
    const float* ln1_b   = (const float*)d_in[base + 3];
    const float* conv1_w = (const float*)d_in[base + 4];
    const float* conv1_b = (const float*)d_in[base + 5];
    const float* conv2_w = (const float*)d_in[base + 6];
    const float* conv2_b = (const float*)d_in[base + 7];
    const float* ln2_g   = (const float*)d_in[base + 8];
    const float* ln2_b   = (const float*)d_in[base + 9];
    const float* post_w  = (const float*)d_in[base + 10];
    const float* post_b  = (const float*)d_in[base + 11];
    const float* w_out   = (const float*)d_in[base + 12];
    const float* b_out   = (const float*)d_in[base + 13];
    float* out = (float*)d_out;

    scan_kernel<<<NB, 1024>>>(ph_bd);
    agg_ln1_kernel<<<dim3(NL, NB), 256>>>(feat, w_attn, b_attn, ln1_g, ln1_b);
    conv1_kernel<<<dim3(NTILES, NB), 256>>>(conv1_w, conv1_b);
    conv2_ln2_kernel<<<dim3(NTILES, NB), 256>>>(conv2_w, conv2_b, ln2_g, ln2_b);
    post_out_kernel<<<dim3(NTILES, NB), 256>>>(post_w, post_b, w_out, b_out, out);
}